// round 6
// baseline (speedup 1.0000x reference)
#include <cuda_runtime.h>
#include <cstdint>

#define NB 512
#define NT 2048
#define NK 8
#define ND 32
#define DTC 0.05f
#define SQDT 0.22360679774997896f  // sqrt(0.05)
#define PF 6                        // prefetch distance (steps)
#define RING 8                      // smem ring slots

// packed fp32x2 FMA (Blackwell-only)
__device__ __forceinline__ unsigned long long ffma2(unsigned long long a,
                                                    unsigned long long b,
                                                    unsigned long long c) {
    unsigned long long d;
    asm("fma.rn.f32x2 %0, %1, %2, %3;" : "=l"(d) : "l"(a), "l"(b), "l"(c));
    return d;
}
__device__ __forceinline__ float2 unpack2(unsigned long long v) {
    float2 r;
    asm("mov.b64 {%0, %1}, %2;" : "=f"(r.x), "=f"(r.y) : "l"(v));
    return r;
}
__device__ __forceinline__ unsigned long long pack2(float lo, float hi) {
    unsigned long long v;
    asm("mov.b64 %0, {%1, %2};" : "=l"(v) : "f"(lo), "f"(hi));
    return v;
}
__device__ __forceinline__ void cp16(uint32_t saddr, const void* gaddr) {
    asm volatile("cp.async.ca.shared.global [%0], [%1], 16;"
                 :: "r"(saddr), "l"(gaddr) : "memory");
}

__global__ void __launch_bounds__(128, 1)
slds_scan_kernel(const float* __restrict__ z0,
                 const float* __restrict__ s_probs,  // [T,B,K]
                 const float* __restrict__ noise,    // [T,B,D]
                 const float* __restrict__ A_s,      // [K,D,D]
                 const float* __restrict__ b_s,      // [K,D]
                 const float* __restrict__ Q_chol,   // [K,D]
                 float* __restrict__ ys)             // [T,B,D]
{
    // per-batch-slot shared state (2 batches per CTA)
    __shared__ __align__(16) float  sm_w[2][RING][8];
    __shared__ __align__(16) float  sm_n[2][RING][ND];
    __shared__ __align__(8)  float2 sm_pq[2][2][ND];   // (p_half, q_half) exchange
    __shared__ __align__(16) float  sm_z[2][2][ND];    // per-warp z broadcast

    const int tid = threadIdx.x;
    const int bh  = tid >> 6;          // batch slot within CTA (0/1)
    const int h   = (tid >> 5) & 1;    // k-half: k in [4h, 4h+4)
    const int i   = tid & 31;          // output dim
    const int b   = blockIdx.x * 2 + bh;
    const int k0  = h * 4;

    // ---- A rows for this (k-half, i) into registers as f32x2 pairs ----
    unsigned long long A2[4][16];
#pragma unroll
    for (int kk = 0; kk < 4; kk++) {
        const ulonglong2* row =
            reinterpret_cast<const ulonglong2*>(A_s + ((size_t)(k0 + kk) * ND + i) * ND);
#pragma unroll
        for (int m = 0; m < 8; m++) {
            ulonglong2 v = row[m];
            A2[kk][2 * m + 0] = v.x;
            A2[kk][2 * m + 1] = v.y;
        }
    }
    // bias folded into accumulator init
    unsigned long long binit[4];
#pragma unroll
    for (int kk = 0; kk < 4; kk++)
        binit[kk] = pack2(b_s[(k0 + kk) * ND + i], 0.0f);
    // this warp's half of Q (diffusion split across warps)
    float Qreg[4];
#pragma unroll
    for (int kk = 0; kk < 4; kk++) Qreg[kk] = Q_chol[(k0 + kk) * ND + i];

    // ---- prefetch ring setup (h==0 warp of each batch slot issues) ----
    const uint32_t s_n = (uint32_t)__cvta_generic_to_shared(&sm_n[bh][0][0]);
    const uint32_t s_w = (uint32_t)__cvta_generic_to_shared(&sm_w[bh][0][0]);
    const float* gn = noise   + (size_t)b * ND;
    const float* gw = s_probs + (size_t)b * NK;

    if (h == 0) {
#pragma unroll
        for (int s = 0; s < PF; s++) {
            if (i < 8)
                cp16(s_n + (uint32_t)(s * ND + i * 4) * 4,
                     gn + (size_t)s * NB * ND + i * 4);
            else if (i < 10)
                cp16(s_w + (uint32_t)(s * 8 + (i - 8) * 4) * 4,
                     gw + (size_t)s * NB * NK + (i - 8) * 4);
            asm volatile("cp.async.commit_group;" ::: "memory");
        }
        asm volatile("cp.async.wait_group %0;" :: "n"(PF - 1) : "memory");
    }

    // ---- initial state ----
    float z = z0[(size_t)b * ND + i];
    sm_z[bh][h][i] = z;
    __syncthreads();   // publishes ring stage 0 AND sm_z

    unsigned long long z2[16];
    {
        const unsigned long long* zz =
            reinterpret_cast<const unsigned long long*>(&sm_z[bh][h][0]);
#pragma unroll
        for (int m = 0; m < 16; m++) z2[m] = zz[m];
    }

    float* yp = ys + (size_t)b * ND + i;

    for (int t = 0; t < NT; t++) {
        const int slot = t & (RING - 1);

        // ---- issue prefetch for stage t+PF (h==0 warps), commit every iter ----
        if (h == 0) {
            const int tp = t + PF;
            if (tp < NT) {
                const int ps = tp & (RING - 1);
                if (i < 8)
                    cp16(s_n + (uint32_t)(ps * ND + i * 4) * 4,
                         gn + (size_t)tp * NB * ND + i * 4);
                else if (i < 10)
                    cp16(s_w + (uint32_t)(ps * 8 + (i - 8) * 4) * 4,
                         gw + (size_t)tp * NB * NK + (i - 8) * 4);
            }
            asm volatile("cp.async.commit_group;" ::: "memory");
        }

        // ---- consume stage t ----
        const float4 wa = *reinterpret_cast<const float4*>(&sm_w[bh][slot][0]);
        const float4 wb = *reinterpret_cast<const float4*>(&sm_w[bh][slot][4]);
        const float  nz = sm_n[bh][slot][i];

        // ---- 4 dot products (bias pre-folded), packed f32x2 ----
        unsigned long long acc0 = binit[0], acc1 = binit[1];
        unsigned long long acc2 = binit[2], acc3 = binit[3];
#pragma unroll
        for (int m = 0; m < 16; m++) {
            acc0 = ffma2(A2[0][m], z2[m], acc0);
            acc1 = ffma2(A2[1][m], z2[m], acc1);
            acc2 = ffma2(A2[2][m], z2[m], acc2);
            acc3 = ffma2(A2[3][m], z2[m], acc3);
        }
        float2 d0 = unpack2(acc0), d1 = unpack2(acc1);
        float2 d2 = unpack2(acc2), d3 = unpack2(acc3);
        const float dot0 = d0.x + d0.y;
        const float dot1 = d1.x + d1.y;
        const float dot2 = d2.x + d2.y;
        const float dot3 = d3.x + d3.y;

        const float wsum = ((wa.x + wa.y) + (wa.z + wa.w)) +
                           ((wb.x + wb.y) + (wb.z + wb.w));
        const float inv = __fdividef(1.0f, wsum);

        float wk0, wk1, wk2, wk3;
        if (h == 0) { wk0 = wa.x; wk1 = wa.y; wk2 = wa.z; wk3 = wa.w; }
        else        { wk0 = wb.x; wk1 = wb.y; wk2 = wb.z; wk3 = wb.w; }

        const float p = wk0 * dot0 + wk1 * dot1 + wk2 * dot2 + wk3 * dot3;
        const float q = wk0 * Qreg[0] + wk1 * Qreg[1] +
                        wk2 * Qreg[2] + wk3 * Qreg[3];

        // ---- cross-warp combine of (p, q); barrier publishes ring t+1 ----
        sm_pq[bh][h][i] = make_float2(p, q);
        if (h == 0)
            asm volatile("cp.async.wait_group %0;" :: "n"(PF - 1) : "memory");
        __syncthreads();
        const float2 other = sm_pq[bh][1 - h][i];
        const float psum = p + other.x;   // identical in both warps
        const float qsum = q + other.y;

        z = z + (DTC * inv) * psum + (qsum * inv) * (SQDT * nz);

        if (h == 0)
            yp[(size_t)t * NB * ND] = z;

        // ---- intra-warp z broadcast ----
        sm_z[bh][h][i] = z;
        __syncwarp();
        const unsigned long long* zz =
            reinterpret_cast<const unsigned long long*>(&sm_z[bh][h][0]);
#pragma unroll
        for (int m = 0; m < 16; m++) z2[m] = zz[m];
    }
}

extern "C" void kernel_launch(void* const* d_in, const int* in_sizes, int n_in,
                              void* d_out, int out_size) {
    const float* z0      = (const float*)d_in[0];
    const float* s_probs = (const float*)d_in[1];
    const float* noise   = (const float*)d_in[2];
    const float* A_s     = (const float*)d_in[3];
    const float* b_s     = (const float*)d_in[4];
    const float* Q_chol  = (const float*)d_in[5];
    float* ys = (float*)d_out;

    slds_scan_kernel<<<NB / 2, 128>>>(z0, s_probs, noise, A_s, b_s, Q_chol, ys);
}

// round 7
// speedup vs baseline: 1.0715x; 1.0715x over previous
#include <cuda_runtime.h>
#include <cstdint>

#define NB 512
#define NT 2048
#define NK 8
#define ND 32
#define DTC 0.05f
#define SQDT 0.22360679774997896f  // sqrt(0.05)
#define PF 6                        // prefetch distance (steps)
#define RING 8                      // smem ring slots

// packed fp32x2 ops (Blackwell-only)
__device__ __forceinline__ unsigned long long ffma2(unsigned long long a,
                                                    unsigned long long b,
                                                    unsigned long long c) {
    unsigned long long d;
    asm("fma.rn.f32x2 %0, %1, %2, %3;" : "=l"(d) : "l"(a), "l"(b), "l"(c));
    return d;
}
__device__ __forceinline__ float2 unpack2(unsigned long long v) {
    float2 r;
    asm("mov.b64 {%0, %1}, %2;" : "=f"(r.x), "=f"(r.y) : "l"(v));
    return r;
}
__device__ __forceinline__ unsigned long long pack2(float lo, float hi) {
    unsigned long long v;
    asm("mov.b64 %0, {%1, %2};" : "=l"(v) : "f"(lo), "f"(hi));
    return v;
}
__device__ __forceinline__ void cp16(uint32_t saddr, const void* gaddr) {
    asm volatile("cp.async.ca.shared.global [%0], [%1], 16;"
                 :: "r"(saddr), "l"(gaddr) : "memory");
}
// barrier scoped to one batch's 2 warps (64 threads); ids 1,2
__device__ __forceinline__ void pair_bar(int id) {
    asm volatile("bar.sync %0, 64;" :: "r"(id) : "memory");
}

__global__ void __launch_bounds__(128, 1)
slds_scan_kernel(const float* __restrict__ z0,
                 const float* __restrict__ s_probs,  // [T,B,K]
                 const float* __restrict__ noise,    // [T,B,D]
                 const float* __restrict__ A_s,      // [K,D,D]
                 const float* __restrict__ b_s,      // [K,D]
                 const float* __restrict__ Q_chol,   // [K,D]
                 float* __restrict__ ys)             // [T,B,D]
{
    // per-batch-slot shared state (2 independent batches per CTA)
    __shared__ __align__(16) float  sm_w[2][RING][8];
    __shared__ __align__(16) float  sm_n[2][RING][ND];
    __shared__ __align__(8)  float2 sm_pq[2][2][ND];   // (p_half, q_half)
    __shared__ __align__(16) float  sm_z[2][2][ND];    // per-warp z copy

    const int tid = threadIdx.x;
    const int bh  = tid >> 6;          // batch slot (0/1)
    const int h   = (tid >> 5) & 1;    // k-half: k in [4h, 4h+4)
    const int i   = tid & 31;          // output dim
    const int b   = blockIdx.x * 2 + bh;
    const int k0  = h * 4;
    const int bar = 1 + bh;            // named barrier id per batch

    // ---- A rows into registers as f32x2 pairs ----
    unsigned long long A2[4][16];
#pragma unroll
    for (int kk = 0; kk < 4; kk++) {
        const ulonglong2* row =
            reinterpret_cast<const ulonglong2*>(A_s + ((size_t)(k0 + kk) * ND + i) * ND);
#pragma unroll
        for (int m = 0; m < 8; m++) {
            ulonglong2 v = row[m];
            A2[kk][2 * m + 0] = v.x;
            A2[kk][2 * m + 1] = v.y;
        }
    }
    // bias folded into even-accumulator init
    unsigned long long binit[4];
#pragma unroll
    for (int kk = 0; kk < 4; kk++)
        binit[kk] = pack2(b_s[(k0 + kk) * ND + i], 0.0f);
    float Qreg[4];
#pragma unroll
    for (int kk = 0; kk < 4; kk++) Qreg[kk] = Q_chol[(k0 + kk) * ND + i];

    // ---- prefetch ring setup ----
    const uint32_t s_n = (uint32_t)__cvta_generic_to_shared(&sm_n[bh][0][0]);
    const uint32_t s_w = (uint32_t)__cvta_generic_to_shared(&sm_w[bh][0][0]);
    const float* gn = noise   + (size_t)b * ND;
    const float* gw = s_probs + (size_t)b * NK;

    if (h == 0) {
#pragma unroll
        for (int s = 0; s < PF; s++) {
            if (i < 8)
                cp16(s_n + (uint32_t)(s * ND + i * 4) * 4,
                     gn + (size_t)s * NB * ND + i * 4);
            else if (i < 10)
                cp16(s_w + (uint32_t)(s * 8 + (i - 8) * 4) * 4,
                     gw + (size_t)s * NB * NK + (i - 8) * 4);
            asm volatile("cp.async.commit_group;" ::: "memory");
        }
        asm volatile("cp.async.wait_group %0;" :: "n"(PF - 1) : "memory");
    }

    // ---- initial state ----
    float z = z0[(size_t)b * ND + i];
    sm_z[bh][h][i] = z;
    __syncthreads();   // once: publishes ring stage 0 + sm_z

    const ulonglong2* zsrc = reinterpret_cast<const ulonglong2*>(&sm_z[bh][h][0]);
    ulonglong2 z4[8];
#pragma unroll
    for (int m = 0; m < 8; m++) z4[m] = zsrc[m];

    float* yp = ys + (size_t)b * ND + i;

#pragma unroll 2
    for (int t = 0; t < NT; t++) {
        const int slot = t & (RING - 1);

        // ---- consume ring stage t (weights + noise) ----
        const float4 wa = *reinterpret_cast<const float4*>(&sm_w[bh][slot][0]);
        const float4 wb = *reinterpret_cast<const float4*>(&sm_w[bh][slot][4]);
        const float  nz = sm_n[bh][slot][i];

        // ---- 4 dots, even/odd split accumulators (chain depth 8) ----
        unsigned long long ae0 = binit[0], ae1 = binit[1];
        unsigned long long ae2 = binit[2], ae3 = binit[3];
        unsigned long long ao0 = 0ull, ao1 = 0ull, ao2 = 0ull, ao3 = 0ull;
#pragma unroll
        for (int m = 0; m < 8; m++) {
            ae0 = ffma2(A2[0][2 * m], z4[m].x, ae0);
            ae1 = ffma2(A2[1][2 * m], z4[m].x, ae1);
            ae2 = ffma2(A2[2][2 * m], z4[m].x, ae2);
            ae3 = ffma2(A2[3][2 * m], z4[m].x, ae3);
            ao0 = ffma2(A2[0][2 * m + 1], z4[m].y, ao0);
            ao1 = ffma2(A2[1][2 * m + 1], z4[m].y, ao1);
            ao2 = ffma2(A2[2][2 * m + 1], z4[m].y, ao2);
            ao3 = ffma2(A2[3][2 * m + 1], z4[m].y, ao3);
        }

        // ---- issue prefetch for stage t+PF (after critical LDS/FFMA kicked off) ----
        if (h == 0) {
            const int tp = t + PF;
            if (tp < NT) {
                const int ps = tp & (RING - 1);
                if (i < 8)
                    cp16(s_n + (uint32_t)(ps * ND + i * 4) * 4,
                         gn + (size_t)tp * NB * ND + i * 4);
                else if (i < 10)
                    cp16(s_w + (uint32_t)(ps * 8 + (i - 8) * 4) * 4,
                         gw + (size_t)tp * NB * NK + (i - 8) * 4);
            }
            asm volatile("cp.async.commit_group;" ::: "memory");
        }

        // per-warp weights + packed copies (off critical path)
        float wk0, wk1, wk2, wk3;
        if (h == 0) { wk0 = wa.x; wk1 = wa.y; wk2 = wa.z; wk3 = wa.w; }
        else        { wk0 = wb.x; wk1 = wb.y; wk2 = wb.z; wk3 = wb.w; }
        const unsigned long long w20 = pack2(wk0, wk0), w21 = pack2(wk1, wk1);
        const unsigned long long w22 = pack2(wk2, wk2), w23 = pack2(wk3, wk3);

        const float wsum = ((wa.x + wa.y) + (wa.z + wa.w)) +
                           ((wb.x + wb.y) + (wb.z + wb.w));
        const float inv = __fdividef(1.0f, wsum);
        const float q = wk0 * Qreg[0] + wk1 * Qreg[1] +
                        wk2 * Qreg[2] + wk3 * Qreg[3];

        // ---- packed weighted reduce: P2 = sum_k w2_k * (ae_k + ao_k) ----
        unsigned long long P2 = 0ull;
        P2 = ffma2(w20, ffma2(ae0, pack2(1.f, 1.f), ao0), P2);  // (ae0+ao0)
        // NOTE: ffma2(x,1,y) = x+y (packed add via fma)
        P2 = ffma2(w21, ffma2(ae1, pack2(1.f, 1.f), ao1), P2);
        P2 = ffma2(w22, ffma2(ae2, pack2(1.f, 1.f), ao2), P2);
        P2 = ffma2(w23, ffma2(ae3, pack2(1.f, 1.f), ao3), P2);
        const float2 pp = unpack2(P2);
        const float p = pp.x + pp.y;

        // ---- exchange (p,q) with partner warp; publish ring t+1 ----
        sm_pq[bh][h][i] = make_float2(p, q);
        if (h == 0)
            asm volatile("cp.async.wait_group %0;" :: "n"(PF - 1) : "memory");
        pair_bar(bar);
        const float2 other = sm_pq[bh][1 - h][i];
        const float psum = p + other.x;   // identical in both warps
        const float qsum = q + other.y;

        z = z + (DTC * inv) * psum + (qsum * inv) * (SQDT * nz);

        if (h == 0)
            yp[(size_t)t * NB * ND] = z;

        // ---- intra-warp z broadcast (own copy; LDS.128 reload) ----
        sm_z[bh][h][i] = z;
        __syncwarp();
#pragma unroll
        for (int m = 0; m < 8; m++) z4[m] = zsrc[m];
    }
}

extern "C" void kernel_launch(void* const* d_in, const int* in_sizes, int n_in,
                              void* d_out, int out_size) {
    const float* z0      = (const float*)d_in[0];
    const float* s_probs = (const float*)d_in[1];
    const float* noise   = (const float*)d_in[2];
    const float* A_s     = (const float*)d_in[3];
    const float* b_s     = (const float*)d_in[4];
    const float* Q_chol  = (const float*)d_in[5];
    float* ys = (float*)d_out;

    slds_scan_kernel<<<NB / 2, 128>>>(z0, s_probs, noise, A_s, b_s, Q_chol, ys);
}